// round 8
// baseline (speedup 1.0000x reference)
#include <cuda_runtime.h>
#include <math.h>

#define NB 512      // batch
#define NT 32       // timesteps
#define ND 512      // depth
#define NC 128      // classes
#define NR 512      // rnn hidden
#define NG 2048     // 4*rnn
#define KX 640      // depth + ncc

typedef unsigned long long ull;

__device__ float g_Z[(size_t)NB * NT * NG];   // 128 MiB
__device__ float g_h[2][NB * NR];
__device__ float g_c[NB * NR];

// ---------------------------------------------------------------------------
__device__ __forceinline__ ull pack2(float x, float y) {
    ull r; asm("mov.b64 %0, {%1, %2};" : "=l"(r) : "f"(x), "f"(y)); return r;
}
__device__ __forceinline__ void unpack2(ull v, float& x, float& y) {
    asm("mov.b64 {%0, %1}, %2;" : "=f"(x), "=f"(y) : "l"(v));
}
__device__ __forceinline__ void ffma2(ull& d, ull a, ull b) {
    asm("fma.rn.f32x2 %0, %1, %2, %0;" : "+l"(d) : "l"(a), "l"(b));
}

// ---------------------------------------------------------------------------
__global__ void k_init() {
    int i = blockIdx.x * blockDim.x + threadIdx.x;
    if (i < NB * NR) { g_h[0][i] = 0.f; g_c[i] = 0.f; }
}

// ---------------------------------------------------------------------------
// Precompute Z = X @ kernel + bias    (M=16384, K=640, N=2048)  [proven]
// ---------------------------------------------------------------------------
__global__ void __launch_bounds__(256, 2) k_precompute(
    const float* __restrict__ f_pool,
    const float* __restrict__ gt,
    const float* __restrict__ W,
    const float* __restrict__ bias)
{
    __shared__ float As[16][128];
    __shared__ float Bs[16][128];
    const int tid = threadIdx.x;
    const int tx = tid & 15, ty = tid >> 4;
    const int m0 = blockIdx.y * 128;
    const int n0 = blockIdx.x * 128;
    const int t  = m0 >> 9;
    const int b0 = m0 & 511;

    ull acc[8][4];
#pragma unroll
    for (int i = 0; i < 8; i++)
#pragma unroll
        for (int p = 0; p < 4; p++) acc[i][p] = 0ull;

    const int aIdx = tid * 2;

    for (int k0 = 0; k0 < KX; k0 += 16) {
#pragma unroll
        for (int l = 0; l < 2; l++) {
            int q   = aIdx + l;
            int row = q >> 2;
            int kq  = (q & 3) << 2;
            int k   = k0 + kq;
            float4 v;
            if (k < ND) {
                v = *(const float4*)(f_pool + ((size_t)(b0 + row) * NT + t) * ND + k);
            } else if (t == 0) {
                v = make_float4(0.f, 0.f, 0.f, 0.f);
            } else {
                v = *(const float4*)(gt + ((size_t)(b0 + row) * NT + (t - 1)) * NC + (k - ND));
            }
            As[kq + 0][row] = v.x; As[kq + 1][row] = v.y;
            As[kq + 2][row] = v.z; As[kq + 3][row] = v.w;
        }
#pragma unroll
        for (int l = 0; l < 2; l++) {
            int q   = aIdx + l;
            int row = q >> 5;
            int cq  = (q & 31) << 2;
            *(float4*)&Bs[row][cq] =
                *(const float4*)(W + (size_t)(k0 + row) * NG + n0 + cq);
        }
        __syncthreads();

#pragma unroll
        for (int k = 0; k < 16; k++) {
            float a[8];
            *(float4*)&a[0] = *(float4*)&As[k][ty * 4];
            *(float4*)&a[4] = *(float4*)&As[k][64 + ty * 4];
            ull bp[4];
            bp[0] = *(const ull*)&Bs[k][tx * 4];
            bp[1] = *(const ull*)&Bs[k][tx * 4 + 2];
            bp[2] = *(const ull*)&Bs[k][64 + tx * 4];
            bp[3] = *(const ull*)&Bs[k][64 + tx * 4 + 2];
            ull ad[8];
#pragma unroll
            for (int i = 0; i < 8; i++) ad[i] = pack2(a[i], a[i]);
#pragma unroll
            for (int i = 0; i < 8; i++)
#pragma unroll
                for (int p = 0; p < 4; p++)
                    ffma2(acc[i][p], ad[i], bp[p]);
        }
        __syncthreads();
    }

#pragma unroll
    for (int ih = 0; ih < 2; ih++)
#pragma unroll
    for (int ii = 0; ii < 4; ii++) {
        int m = m0 + ih * 64 + ty * 4 + ii;
        int i = ih * 4 + ii;
#pragma unroll
        for (int jh = 0; jh < 2; jh++) {
            int n = n0 + jh * 64 + tx * 4;
            float4 v;
            unpack2(acc[i][jh * 2 + 0], v.x, v.y);
            unpack2(acc[i][jh * 2 + 1], v.z, v.w);
            v.x += bias[n + 0]; v.y += bias[n + 1];
            v.z += bias[n + 2]; v.w += bias[n + 3];
            *(float4*)&g_Z[(size_t)m * NG + n] = v;
        }
    }
}

// ---------------------------------------------------------------------------
// Fused smem overlay (256-thread roles). Max ≈ 16.6 KB.
// ---------------------------------------------------------------------------
union FusedSM {
    struct { float2 As2[16][66]; float Bs[16][128]; } s;       // step: 16,640 B
    struct { float2 hsp[2][NR]; float2 part[2][NC];
             float lgs[4][NC]; int amax[4]; } l;               // logits: 12,304 B
};

// ---------------------------------------------------------------------------
// Step role (256 thr): tile 64b x 32j x 4g, FFMA2, pre-dup A pairs.
// 128 blocks: bid = row-group*16 + j-group.
// ---------------------------------------------------------------------------
__device__ void do_step(FusedSM& sm, const float* __restrict__ rec,
                        int t, int bid)
{
    const int tid = threadIdx.x;          // 256
    const int tx = tid & 15, ty = tid >> 4;
    const int b0 = (bid >> 4) * 64;
    const int j0 = (bid & 15) * 32;
    const int bufin = t & 1;
    const float* __restrict__ h_in = g_h[bufin];
    float* __restrict__ h_out = g_h[bufin ^ 1];

    ull acc[4][4];
#pragma unroll
    for (int r = 0; r < 4; r++)
#pragma unroll
        for (int g = 0; g < 4; g++) acc[r][g] = 0ull;

    for (int k0 = 0; k0 < NR; k0 += 16) {
        {   // A: 64 rows x 16 k, pre-duplicated {v,v}
            int row = tid >> 2;
            int kq  = (tid & 3) << 2;
            float4 v = *(const float4*)(h_in + (size_t)(b0 + row) * NR + k0 + kq);
            sm.s.As2[kq + 0][row] = make_float2(v.x, v.x);
            sm.s.As2[kq + 1][row] = make_float2(v.y, v.y);
            sm.s.As2[kq + 2][row] = make_float2(v.z, v.z);
            sm.s.As2[kq + 3][row] = make_float2(v.w, v.w);
        }
#pragma unroll
        for (int l = 0; l < 2; l++) {   // B: Bs[k][g*32+jj]
            int q   = tid * 2 + l;
            int row = q >> 5;
            int e   = (q & 31) << 2;
            int g   = e >> 5;
            int jj  = e & 31;
            *(float4*)&sm.s.Bs[row][e] =
                *(const float4*)(rec + (size_t)(k0 + row) * NG + g * NR + j0 + jj);
        }
        __syncthreads();

#pragma unroll
        for (int k = 0; k < 16; k++) {
            ull ad[4], bp[4];
#pragma unroll
            for (int r = 0; r < 4; r++)
                ad[r] = *(const ull*)&sm.s.As2[k][ty * 4 + r];
#pragma unroll
            for (int g = 0; g < 4; g++)
                bp[g] = *(const ull*)&sm.s.Bs[k][g * 32 + tx * 2];
#pragma unroll
            for (int r = 0; r < 4; r++)
#pragma unroll
                for (int g = 0; g < 4; g++)
                    ffma2(acc[r][g], ad[r], bp[g]);
        }
        __syncthreads();
    }

    const int j = j0 + tx * 2;
#pragma unroll
    for (int r = 0; r < 4; r++) {
        int b = b0 + ty * 4 + r;
        size_t zb = ((size_t)t * NB + b) * NG + j;
        float2 zi = *(const float2*)&g_Z[zb];
        float2 zf = *(const float2*)&g_Z[zb + NR];
        float2 zg = *(const float2*)&g_Z[zb + 2 * NR];
        float2 zo = *(const float2*)&g_Z[zb + 3 * NR];
        float ai0, ai1, af0, af1, ag0, ag1, ao0, ao1;
        unpack2(acc[r][0], ai0, ai1);
        unpack2(acc[r][1], af0, af1);
        unpack2(acc[r][2], ag0, ag1);
        unpack2(acc[r][3], ao0, ao1);
        int ci = b * NR + j;
        float2 cold = *(const float2*)&g_c[ci];
        float2 cn, hn;
        {
            float vi = zi.x + ai0, vf = zf.x + af0, vg = zg.x + ag0, vo = zo.x + ao0;
            float si = 1.f / (1.f + expf(-vi));
            float sf = 1.f / (1.f + expf(-vf));
            float so = 1.f / (1.f + expf(-vo));
            float tg = tanhf(vg);
            cn.x = sf * cold.x + si * tg;
            hn.x = so * tanhf(cn.x);
        }
        {
            float vi = zi.y + ai1, vf = zf.y + af1, vg = zg.y + ag1, vo = zo.y + ao1;
            float si = 1.f / (1.f + expf(-vi));
            float sf = 1.f / (1.f + expf(-vf));
            float so = 1.f / (1.f + expf(-vo));
            float tg = tanhf(vg);
            cn.y = sf * cold.y + si * tg;
            hn.y = so * tanhf(cn.y);
        }
        *(float2*)&g_c[ci] = cn;
        *(float2*)&h_out[ci] = hn;
    }
}

// ---------------------------------------------------------------------------
// Logits role (256 thr): 4 rows/block, 2-way k-split (proven R5 v2).
// lt = timestep emitted; reads g_h[(lt+1)&1].
// ---------------------------------------------------------------------------
__device__ void do_logits(FusedSM& sm,
                          const float* __restrict__ sw,
                          const float* __restrict__ sb,
                          float* __restrict__ out, int lt, int lbid)
{
    const int tid = threadIdx.x;          // 256
    const int j   = tid & 127;
    const int kq  = tid >> 7;             // 0/1
    const int b0  = lbid * 4;
    const float* __restrict__ h = g_h[(lt + 1) & 1];

#pragma unroll
    for (int r = 0; r < 4; r++) {
#pragma unroll
        for (int kk = 0; kk < 2; kk++) {
            int k = tid + kk * 256;
            float v = h[(size_t)(b0 + r) * NR + k];
            ((float*)&sm.l.hsp[r >> 1][k])[r & 1] = v;
        }
    }
    __syncthreads();

    ull lacc[2] = {0ull, 0ull};
    const int kbase = kq << 8;
#pragma unroll 8
    for (int kk = 0; kk < 256; kk++) {
        int k = kbase + kk;
        float w = sw[(size_t)k * NC + j];
        ull wd = pack2(w, w);
        ffma2(lacc[0], wd, *(const ull*)&sm.l.hsp[0][k]);
        ffma2(lacc[1], wd, *(const ull*)&sm.l.hsp[1][k]);
    }
    if (kq) {
#pragma unroll
        for (int p = 0; p < 2; p++) {
            float x, y; unpack2(lacc[p], x, y);
            sm.l.part[p][j] = make_float2(x, y);
        }
    }
    __syncthreads();
    if (!kq) {
        float bj = sb[j];
#pragma unroll
        for (int p = 0; p < 2; p++) {
            float x, y; unpack2(lacc[p], x, y);
            float2 p1 = sm.l.part[p][j];
            sm.l.lgs[2 * p + 0][j] = x + p1.x + bj;
            sm.l.lgs[2 * p + 1][j] = y + p1.y + bj;
        }
    }
    __syncthreads();

    const int wid = tid >> 5, lane = tid & 31;
    if (wid < 4) {
        float best = -INFINITY; int bi = 0;
        int cbase = lane * 4;
#pragma unroll
        for (int cc = 0; cc < 4; cc++) {
            float v = sm.l.lgs[wid][cbase + cc];
            if (v > best) { best = v; bi = cbase + cc; }
        }
#pragma unroll
        for (int off = 16; off; off >>= 1) {
            float ov = __shfl_down_sync(0xffffffffu, best, off);
            int   oi = __shfl_down_sync(0xffffffffu, bi,   off);
            if (ov > best || (ov == best && oi < bi)) { best = ov; bi = oi; }
        }
        if (lane == 0) sm.l.amax[wid] = bi;
    }
    __syncthreads();

#pragma unroll
    for (int rr = 0; rr < 2; rr++) {
        int r = kq * 2 + rr;
        out[((size_t)(b0 + r) * NT + lt) * NC + j] = (j == sm.l.amax[r]) ? 1.f : 0.f;
    }
}

// ---------------------------------------------------------------------------
// Fused: 256 blocks x 256 thr. bid<128 -> step(t); bid>=128 -> logits(t-1).
// All blocks co-resident (>=2 blocks/SM) -> no wave tail.
// ---------------------------------------------------------------------------
__global__ void __launch_bounds__(256) k_fused(
    const float* __restrict__ rec,
    const float* __restrict__ sw,
    const float* __restrict__ sb,
    float* __restrict__ out, int t)
{
    __shared__ FusedSM sm;
    const int bid = blockIdx.x;
    if (bid < 128) {
        do_step(sm, rec, t, bid);
    } else if (t > 0) {
        do_logits(sm, sw, sb, out, t - 1, bid - 128);
    }
}

// Tail logits for t = NT-1 (128 blocks x 256 thr)
__global__ void __launch_bounds__(256) k_logits_tail(
    const float* __restrict__ sw,
    const float* __restrict__ sb,
    float* __restrict__ out)
{
    __shared__ FusedSM sm;
    do_logits(sm, sw, sb, out, NT - 1, blockIdx.x);
}

// ---------------------------------------------------------------------------
__global__ void k_finalize(float* __restrict__ out)
{
    int i = blockIdx.x * blockDim.x + threadIdx.x;
    if (i < NB * NR) {
        out[(size_t)NB * NT * NC + i]           = g_h[0][i];   // NT&1 == 0
        out[(size_t)NB * NT * NC + NB * NR + i] = g_c[i];
    }
}

// ---------------------------------------------------------------------------
extern "C" void kernel_launch(void* const* d_in, const int* in_sizes, int n_in,
                              void* d_out, int out_size)
{
    const float* f_pool = (const float*)d_in[0];
    const float* gt     = (const float*)d_in[1];
    const float* W      = (const float*)d_in[2];
    const float* rec    = (const float*)d_in[3];
    const float* bias   = (const float*)d_in[4];
    const float* sw     = (const float*)d_in[5];
    const float* sb     = (const float*)d_in[6];
    float* out = (float*)d_out;

    k_init<<<(NB * NR + 255) / 256, 256>>>();
    k_precompute<<<dim3(16, 128), 256>>>(f_pool, gt, W, bias);
    for (int t = 0; t < NT; t++)
        k_fused<<<256, 256>>>(rec, sw, sb, out, t);
    k_logits_tail<<<128, 256>>>(sw, sb, out);
    k_finalize<<<(NB * NR + 255) / 256, 256>>>(out);
}

// round 9
// speedup vs baseline: 1.1023x; 1.1023x over previous
#include <cuda_runtime.h>
#include <math.h>

#define NB 512      // batch
#define NT 32       // timesteps
#define ND 512      // depth
#define NC 128      // classes
#define NR 512      // rnn hidden
#define NG 2048     // 4*rnn
#define KX 640      // depth + ncc

typedef unsigned long long ull;

__device__ float g_Z[(size_t)NB * NT * NG];   // 128 MiB
__device__ float g_h[2][NB * NR];
__device__ float g_c[NB * NR];

// ---------------------------------------------------------------------------
__device__ __forceinline__ ull pack2(float x, float y) {
    ull r; asm("mov.b64 %0, {%1, %2};" : "=l"(r) : "f"(x), "f"(y)); return r;
}
__device__ __forceinline__ void unpack2(ull v, float& x, float& y) {
    asm("mov.b64 {%0, %1}, %2;" : "=f"(x), "=f"(y) : "l"(v));
}
__device__ __forceinline__ void ffma2(ull& d, ull a, ull b) {
    asm("fma.rn.f32x2 %0, %1, %2, %0;" : "+l"(d) : "l"(a), "l"(b));
}
__device__ __forceinline__ void fadd2(ull& d, ull a) {
    asm("add.rn.f32x2 %0, %0, %1;" : "+l"(d) : "l"(a));
}

// ---------------------------------------------------------------------------
__global__ void k_init() {
    int i = blockIdx.x * blockDim.x + threadIdx.x;
    if (i < NB * NR) { g_h[0][i] = 0.f; g_c[i] = 0.f; }
}

// ---------------------------------------------------------------------------
// Precompute Z = X @ kernel + bias    (M=16384, K=640, N=2048)  [proven]
// ---------------------------------------------------------------------------
__global__ void __launch_bounds__(256, 2) k_precompute(
    const float* __restrict__ f_pool,
    const float* __restrict__ gt,
    const float* __restrict__ W,
    const float* __restrict__ bias)
{
    __shared__ float As[16][128];
    __shared__ float Bs[16][128];
    const int tid = threadIdx.x;
    const int tx = tid & 15, ty = tid >> 4;
    const int m0 = blockIdx.y * 128;
    const int n0 = blockIdx.x * 128;
    const int t  = m0 >> 9;
    const int b0 = m0 & 511;

    ull acc[8][4];
#pragma unroll
    for (int i = 0; i < 8; i++)
#pragma unroll
        for (int p = 0; p < 4; p++) acc[i][p] = 0ull;

    const int aIdx = tid * 2;

    for (int k0 = 0; k0 < KX; k0 += 16) {
#pragma unroll
        for (int l = 0; l < 2; l++) {
            int q   = aIdx + l;
            int row = q >> 2;
            int kq  = (q & 3) << 2;
            int k   = k0 + kq;
            float4 v;
            if (k < ND) {
                v = *(const float4*)(f_pool + ((size_t)(b0 + row) * NT + t) * ND + k);
            } else if (t == 0) {
                v = make_float4(0.f, 0.f, 0.f, 0.f);
            } else {
                v = *(const float4*)(gt + ((size_t)(b0 + row) * NT + (t - 1)) * NC + (k - ND));
            }
            As[kq + 0][row] = v.x; As[kq + 1][row] = v.y;
            As[kq + 2][row] = v.z; As[kq + 3][row] = v.w;
        }
#pragma unroll
        for (int l = 0; l < 2; l++) {
            int q   = aIdx + l;
            int row = q >> 5;
            int cq  = (q & 31) << 2;
            *(float4*)&Bs[row][cq] =
                *(const float4*)(W + (size_t)(k0 + row) * NG + n0 + cq);
        }
        __syncthreads();

#pragma unroll
        for (int k = 0; k < 16; k++) {
            float a[8];
            *(float4*)&a[0] = *(float4*)&As[k][ty * 4];
            *(float4*)&a[4] = *(float4*)&As[k][64 + ty * 4];
            ull bp[4];
            bp[0] = *(const ull*)&Bs[k][tx * 4];
            bp[1] = *(const ull*)&Bs[k][tx * 4 + 2];
            bp[2] = *(const ull*)&Bs[k][64 + tx * 4];
            bp[3] = *(const ull*)&Bs[k][64 + tx * 4 + 2];
            ull ad[8];
#pragma unroll
            for (int i = 0; i < 8; i++) ad[i] = pack2(a[i], a[i]);
#pragma unroll
            for (int i = 0; i < 8; i++)
#pragma unroll
                for (int p = 0; p < 4; p++)
                    ffma2(acc[i][p], ad[i], bp[p]);
        }
        __syncthreads();
    }

#pragma unroll
    for (int ih = 0; ih < 2; ih++)
#pragma unroll
    for (int ii = 0; ii < 4; ii++) {
        int m = m0 + ih * 64 + ty * 4 + ii;
        int i = ih * 4 + ii;
#pragma unroll
        for (int jh = 0; jh < 2; jh++) {
            int n = n0 + jh * 64 + tx * 4;
            float4 v;
            unpack2(acc[i][jh * 2 + 0], v.x, v.y);
            unpack2(acc[i][jh * 2 + 1], v.z, v.w);
            v.x += bias[n + 0]; v.y += bias[n + 1];
            v.z += bias[n + 2]; v.w += bias[n + 3];
            *(float4*)&g_Z[(size_t)m * NG + n] = v;
        }
    }
}

// ---------------------------------------------------------------------------
// Shared-memory overlay (512-thread roles, ~33.3 KB max)
// ---------------------------------------------------------------------------
union FusedSM {
    struct { float2 As2[2][16][66]; float Bs[2][16][128]; } s;   // step
    ull red[16][256];                                            // step reduce
    struct { float2 hsp[4][NR]; float2 part[3][4][NC];
             float lgs[8][NC]; int amax[8]; } l;                 // logits
};

// ---------------------------------------------------------------------------
// Step role (proven step v2): 512 thr, 2-way k-split, register prefetch.
// ---------------------------------------------------------------------------
__device__ void do_step(FusedSM& sm, const float* __restrict__ rec,
                        int t, int bid)
{
    const int tid  = threadIdx.x;
    const int kh   = tid >> 8;
    const int tidh = tid & 255;
    const int tx = tidh & 15, ty = tidh >> 4;
    const int b0 = (bid >> 4) * 64;
    const int j0 = (bid & 15) * 32;
    const int kbase = kh << 8;
    const int bufin = t & 1;
    const float* __restrict__ h_in = g_h[bufin];
    float* __restrict__ h_out = g_h[bufin ^ 1];

    ull acc[4][4];
#pragma unroll
    for (int r = 0; r < 4; r++)
#pragma unroll
        for (int g = 0; g < 4; g++) acc[r][g] = 0ull;

    const int arow = tidh >> 2;
    const int akq  = (tidh & 3) << 2;
    const int q0 = tidh * 2, q1 = q0 + 1;
    const int brow0 = q0 >> 5, be0 = (q0 & 31) << 2;
    const int brow1 = q1 >> 5, be1 = (q1 & 31) << 2;
    const int bg0 = be0 >> 5, bj0 = be0 & 31;
    const int bg1 = be1 >> 5, bj1 = be1 & 31;
    const float* aptr = h_in + (size_t)(b0 + arow) * NR + kbase + akq;
    const float* bptr0 = rec + (size_t)(kbase + brow0) * NG + bg0 * NR + j0 + bj0;
    const float* bptr1 = rec + (size_t)(kbase + brow1) * NG + bg1 * NR + j0 + bj1;

    float4 areg = *(const float4*)aptr;
    float4 breg0 = *(const float4*)bptr0;
    float4 breg1 = *(const float4*)bptr1;

    for (int tile = 0; tile < 16; tile++) {
        sm.s.As2[kh][akq + 0][arow] = make_float2(areg.x, areg.x);
        sm.s.As2[kh][akq + 1][arow] = make_float2(areg.y, areg.y);
        sm.s.As2[kh][akq + 2][arow] = make_float2(areg.z, areg.z);
        sm.s.As2[kh][akq + 3][arow] = make_float2(areg.w, areg.w);
        *(float4*)&sm.s.Bs[kh][brow0][be0] = breg0;
        *(float4*)&sm.s.Bs[kh][brow1][be1] = breg1;
        __syncthreads();

        if (tile < 15) {
            int koff = (tile + 1) * 16;
            areg  = *(const float4*)(aptr + koff);
            breg0 = *(const float4*)(bptr0 + (size_t)koff * NG);
            breg1 = *(const float4*)(bptr1 + (size_t)koff * NG);
        }

#pragma unroll
        for (int k = 0; k < 16; k++) {
            ull ad[4], bp[4];
#pragma unroll
            for (int r = 0; r < 4; r++)
                ad[r] = *(const ull*)&sm.s.As2[kh][k][ty * 4 + r];
#pragma unroll
            for (int g = 0; g < 4; g++)
                bp[g] = *(const ull*)&sm.s.Bs[kh][k][g * 32 + tx * 2];
#pragma unroll
            for (int r = 0; r < 4; r++)
#pragma unroll
                for (int g = 0; g < 4; g++)
                    ffma2(acc[r][g], ad[r], bp[g]);
        }
        __syncthreads();
    }

    if (kh) {
#pragma unroll
        for (int r = 0; r < 4; r++)
#pragma unroll
            for (int g = 0; g < 4; g++)
                sm.red[r * 4 + g][tidh] = acc[r][g];
    }
    __syncthreads();
    if (!kh) {
#pragma unroll
        for (int r = 0; r < 4; r++)
#pragma unroll
            for (int g = 0; g < 4; g++)
                fadd2(acc[r][g], sm.red[r * 4 + g][tidh]);

        const int j = j0 + tx * 2;
#pragma unroll
        for (int r = 0; r < 4; r++) {
            int b = b0 + ty * 4 + r;
            size_t zb = ((size_t)t * NB + b) * NG + j;
            float2 zi = *(const float2*)&g_Z[zb];
            float2 zf = *(const float2*)&g_Z[zb + NR];
            float2 zg = *(const float2*)&g_Z[zb + 2 * NR];
            float2 zo = *(const float2*)&g_Z[zb + 3 * NR];
            float ai0, ai1, af0, af1, ag0, ag1, ao0, ao1;
            unpack2(acc[r][0], ai0, ai1);
            unpack2(acc[r][1], af0, af1);
            unpack2(acc[r][2], ag0, ag1);
            unpack2(acc[r][3], ao0, ao1);
            int ci = b * NR + j;
            float2 cold = *(const float2*)&g_c[ci];
            float2 cn, hn;
            {
                float vi = zi.x + ai0, vf = zf.x + af0, vg = zg.x + ag0, vo = zo.x + ao0;
                float si = 1.f / (1.f + expf(-vi));
                float sf = 1.f / (1.f + expf(-vf));
                float so = 1.f / (1.f + expf(-vo));
                float tg = tanhf(vg);
                cn.x = sf * cold.x + si * tg;
                hn.x = so * tanhf(cn.x);
            }
            {
                float vi = zi.y + ai1, vf = zf.y + af1, vg = zg.y + ag1, vo = zo.y + ao1;
                float si = 1.f / (1.f + expf(-vi));
                float sf = 1.f / (1.f + expf(-vf));
                float so = 1.f / (1.f + expf(-vo));
                float tg = tanhf(vg);
                cn.y = sf * cold.y + si * tg;
                hn.y = so * tanhf(cn.y);
            }
            *(float2*)&g_c[ci] = cn;
            *(float2*)&h_out[ci] = hn;
        }
    }
}

// ---------------------------------------------------------------------------
// Logits role: 32 rows/block as 4 groups of 8 (proven 8-row body looped).
// 16 blocks cover 512 rows. lt = timestep emitted; reads g_h[(lt+1)&1].
// ---------------------------------------------------------------------------
__device__ void do_logits(FusedSM& sm,
                          const float* __restrict__ sw,
                          const float* __restrict__ sb,
                          float* __restrict__ out, int lt, int lbid)
{
    const int tid = threadIdx.x;          // 512
    const int j   = tid & 127;
    const int kq  = tid >> 7;             // 0..3
    const float* __restrict__ h = g_h[(lt + 1) & 1];
    const float bj = sb[j];

    for (int grp = 0; grp < 4; grp++) {
        const int b0 = lbid * 32 + grp * 8;

#pragma unroll
        for (int r = 0; r < 8; r++) {
            float v = h[(size_t)(b0 + r) * NR + tid];
            ((float*)&sm.l.hsp[r >> 1][tid])[r & 1] = v;
        }
        __syncthreads();

        ull acc[4] = {0ull, 0ull, 0ull, 0ull};
        const int kbase = kq << 7;
#pragma unroll 8
        for (int kk = 0; kk < 128; kk++) {
            int k = kbase + kk;
            float w = sw[(size_t)k * NC + j];
            ull wd = pack2(w, w);
#pragma unroll
            for (int p = 0; p < 4; p++)
                ffma2(acc[p], wd, *(const ull*)&sm.l.hsp[p][k]);
        }
        if (kq) {
#pragma unroll
            for (int p = 0; p < 4; p++) {
                float x, y; unpack2(acc[p], x, y);
                sm.l.part[kq - 1][p][j] = make_float2(x, y);
            }
        }
        __syncthreads();
        if (!kq) {
#pragma unroll
            for (int p = 0; p < 4; p++) {
                float x, y; unpack2(acc[p], x, y);
                float2 p0 = sm.l.part[0][p][j], p1 = sm.l.part[1][p][j], p2 = sm.l.part[2][p][j];
                sm.l.lgs[2 * p + 0][j] = x + p0.x + p1.x + p2.x + bj;
                sm.l.lgs[2 * p + 1][j] = y + p0.y + p1.y + p2.y + bj;
            }
        }
        __syncthreads();

        const int wid = tid >> 5, lane = tid & 31;
        if (wid < 8) {
            float best = -INFINITY; int bi = 0;
            int cbase = lane * 4;
#pragma unroll
            for (int cc = 0; cc < 4; cc++) {
                float v = sm.l.lgs[wid][cbase + cc];
                if (v > best) { best = v; bi = cbase + cc; }
            }
#pragma unroll
            for (int off = 16; off; off >>= 1) {
                float ov = __shfl_down_sync(0xffffffffu, best, off);
                int   oi = __shfl_down_sync(0xffffffffu, bi,   off);
                if (ov > best || (ov == best && oi < bi)) { best = ov; bi = oi; }
            }
            if (lane == 0) sm.l.amax[wid] = bi;
        }
        __syncthreads();

#pragma unroll
        for (int rr = 0; rr < 2; rr++) {
            int r = kq + rr * 4;
            out[((size_t)(b0 + r) * NT + lt) * NC + j] = (j == sm.l.amax[r]) ? 1.f : 0.f;
        }
        __syncthreads();   // protect hsp/amax before next group staging
    }
}

// ---------------------------------------------------------------------------
// Fused: 144 blocks x 512 thr (single wave on 148 SMs).
// bid<128 -> step(t); bid>=128 -> logits(t-1) (32 rows each).
// ---------------------------------------------------------------------------
__global__ void __launch_bounds__(512) k_fused(
    const float* __restrict__ rec,
    const float* __restrict__ sw,
    const float* __restrict__ sb,
    float* __restrict__ out, int t)
{
    __shared__ FusedSM sm;
    const int bid = blockIdx.x;
    if (bid < 128) {
        do_step(sm, rec, t, bid);
    } else if (t > 0) {
        do_logits(sm, sw, sb, out, t - 1, bid - 128);
    }
}

// Tail logits for t = NT-1 (16 blocks x 512 thr)
__global__ void __launch_bounds__(512) k_logits_tail(
    const float* __restrict__ sw,
    const float* __restrict__ sb,
    float* __restrict__ out)
{
    __shared__ FusedSM sm;
    do_logits(sm, sw, sb, out, NT - 1, blockIdx.x);
}

// ---------------------------------------------------------------------------
__global__ void k_finalize(float* __restrict__ out)
{
    int i = blockIdx.x * blockDim.x + threadIdx.x;
    if (i < NB * NR) {
        out[(size_t)NB * NT * NC + i]           = g_h[0][i];   // NT&1 == 0
        out[(size_t)NB * NT * NC + NB * NR + i] = g_c[i];
    }
}

// ---------------------------------------------------------------------------
extern "C" void kernel_launch(void* const* d_in, const int* in_sizes, int n_in,
                              void* d_out, int out_size)
{
    const float* f_pool = (const float*)d_in[0];
    const float* gt     = (const float*)d_in[1];
    const float* W      = (const float*)d_in[2];
    const float* rec    = (const float*)d_in[3];
    const float* bias   = (const float*)d_in[4];
    const float* sw     = (const float*)d_in[5];
    const float* sb     = (const float*)d_in[6];
    float* out = (float*)d_out;

    k_init<<<(NB * NR + 255) / 256, 256>>>();
    k_precompute<<<dim3(16, 128), 256>>>(f_pool, gt, W, bias);
    for (int t = 0; t < NT; t++)
        k_fused<<<144, 512>>>(rec, sw, sb, out, t);
    k_logits_tail<<<16, 512>>>(sw, sb, out);
    k_finalize<<<(NB * NR + 255) / 256, 256>>>(out);
}

// round 12
// speedup vs baseline: 1.1326x; 1.0275x over previous
#include <cuda_runtime.h>
#include <math.h>

#define NB 512      // batch
#define NT 32       // timesteps
#define ND 512      // depth
#define NC 128      // classes
#define NR 512      // rnn hidden
#define NG 2048     // 4*rnn
#define KX 640      // depth + ncc

typedef unsigned long long ull;

__device__ float g_Z[(size_t)NB * NT * NG];   // 128 MiB
__device__ float g_P[2][(size_t)NB * NG];     // 8 MiB partial gate sums
__device__ float g_h[2][NB * NR];
__device__ float g_c[NB * NR];

// ---------------------------------------------------------------------------
__device__ __forceinline__ ull pack2(float x, float y) {
    ull r; asm("mov.b64 %0, {%1, %2};" : "=l"(r) : "f"(x), "f"(y)); return r;
}
__device__ __forceinline__ void unpack2(ull v, float& x, float& y) {
    asm("mov.b64 {%0, %1}, %2;" : "=f"(x), "=f"(y) : "l"(v));
}
__device__ __forceinline__ void ffma2(ull& d, ull a, ull b) {
    asm("fma.rn.f32x2 %0, %1, %2, %0;" : "+l"(d) : "l"(a), "l"(b));
}

// ---------------------------------------------------------------------------
__global__ void k_init() {
    int i = blockIdx.x * blockDim.x + threadIdx.x;
    if (i < NB * NR) { g_h[0][i] = 0.f; g_c[i] = 0.f; }
}

// ---------------------------------------------------------------------------
// Precompute Z = X @ kernel + bias    (M=16384, K=640, N=2048)  [proven]
// ---------------------------------------------------------------------------
__global__ void __launch_bounds__(256, 2) k_precompute(
    const float* __restrict__ f_pool,
    const float* __restrict__ gt,
    const float* __restrict__ W,
    const float* __restrict__ bias)
{
    __shared__ float As[16][128];
    __shared__ float Bs[16][128];
    const int tid = threadIdx.x;
    const int tx = tid & 15, ty = tid >> 4;
    const int m0 = blockIdx.y * 128;
    const int n0 = blockIdx.x * 128;
    const int t  = m0 >> 9;
    const int b0 = m0 & 511;

    ull acc[8][4];
#pragma unroll
    for (int i = 0; i < 8; i++)
#pragma unroll
        for (int p = 0; p < 4; p++) acc[i][p] = 0ull;

    const int aIdx = tid * 2;

    for (int k0 = 0; k0 < KX; k0 += 16) {
#pragma unroll
        for (int l = 0; l < 2; l++) {
            int q   = aIdx + l;
            int row = q >> 2;
            int kq  = (q & 3) << 2;
            int k   = k0 + kq;
            float4 v;
            if (k < ND) {
                v = *(const float4*)(f_pool + ((size_t)(b0 + row) * NT + t) * ND + k);
            } else if (t == 0) {
                v = make_float4(0.f, 0.f, 0.f, 0.f);
            } else {
                v = *(const float4*)(gt + ((size_t)(b0 + row) * NT + (t - 1)) * NC + (k - ND));
            }
            As[kq + 0][row] = v.x; As[kq + 1][row] = v.y;
            As[kq + 2][row] = v.z; As[kq + 3][row] = v.w;
        }
#pragma unroll
        for (int l = 0; l < 2; l++) {
            int q   = aIdx + l;
            int row = q >> 5;
            int cq  = (q & 31) << 2;
            *(float4*)&Bs[row][cq] =
                *(const float4*)(W + (size_t)(k0 + row) * NG + n0 + cq);
        }
        __syncthreads();

#pragma unroll
        for (int k = 0; k < 16; k++) {
            float a[8];
            *(float4*)&a[0] = *(float4*)&As[k][ty * 4];
            *(float4*)&a[4] = *(float4*)&As[k][64 + ty * 4];
            ull bp[4];
            bp[0] = *(const ull*)&Bs[k][tx * 4];
            bp[1] = *(const ull*)&Bs[k][tx * 4 + 2];
            bp[2] = *(const ull*)&Bs[k][64 + tx * 4];
            bp[3] = *(const ull*)&Bs[k][64 + tx * 4 + 2];
            ull ad[8];
#pragma unroll
            for (int i = 0; i < 8; i++) ad[i] = pack2(a[i], a[i]);
#pragma unroll
            for (int i = 0; i < 8; i++)
#pragma unroll
                for (int p = 0; p < 4; p++)
                    ffma2(acc[i][p], ad[i], bp[p]);
        }
        __syncthreads();
    }

#pragma unroll
    for (int ih = 0; ih < 2; ih++)
#pragma unroll
    for (int ii = 0; ii < 4; ii++) {
        int m = m0 + ih * 64 + ty * 4 + ii;
        int i = ih * 4 + ii;
#pragma unroll
        for (int jh = 0; jh < 2; jh++) {
            int n = n0 + jh * 64 + tx * 4;
            float4 v;
            unpack2(acc[i][jh * 2 + 0], v.x, v.y);
            unpack2(acc[i][jh * 2 + 1], v.z, v.w);
            v.x += bias[n + 0]; v.y += bias[n + 1];
            v.z += bias[n + 2]; v.w += bias[n + 3];
            *(float4*)&g_Z[(size_t)m * NG + n] = v;
        }
    }
}

// ---------------------------------------------------------------------------
// Shared overlay for k_gemm (GEMM role 16 KB; logits role ~24.6 KB)
// ---------------------------------------------------------------------------
union GemmSM {
    struct { float As[16][128]; float Bs[16][128]; } g;
    struct { float2 hsp[4][NR]; float2 part[4][NC];
             float lgs[8][NC]; int amax[8]; } l;
};

// ---------------------------------------------------------------------------
// GEMM role: partial h @ rec over one K-chunk of 256.
// 128x128 tile, 8x8/thread, BK=16, register prefetch.
// bid: chunk = bid>>6, tile = bid&63 (mtile = tile>>4, ntile = tile&15).
// ---------------------------------------------------------------------------
__device__ void do_gemm(GemmSM& sm, const float* __restrict__ rec,
                        int t, int bid)
{
    const int tid = threadIdx.x;          // 256
    const int tx = tid & 15, ty = tid >> 4;
    const int chunk = bid >> 6;
    const int tile  = bid & 63;
    const int m0 = (tile >> 4) * 128;
    const int n0 = (tile & 15) * 128;
    const int kb = chunk * 256;
    const float* __restrict__ h_in = g_h[t & 1];
    float* __restrict__ P = g_P[chunk];

    ull acc[8][4];
#pragma unroll
    for (int i = 0; i < 8; i++)
#pragma unroll
        for (int p = 0; p < 4; p++) acc[i][p] = 0ull;

    const int q0 = tid * 2, q1 = q0 + 1;
    const int ar0 = q0 >> 2, ak0 = (q0 & 3) << 2;
    const int ar1 = q1 >> 2, ak1 = (q1 & 3) << 2;
    const int br0 = q0 >> 5, bc0 = (q0 & 31) << 2;
    const int br1 = q1 >> 5, bc1 = (q1 & 31) << 2;
    const float* ap0 = h_in + (size_t)(m0 + ar0) * NR + kb + ak0;
    const float* ap1 = h_in + (size_t)(m0 + ar1) * NR + kb + ak1;
    const float* bq0 = rec + (size_t)(kb + br0) * NG + n0 + bc0;
    const float* bq1 = rec + (size_t)(kb + br1) * NG + n0 + bc1;

    float4 ra0 = *(const float4*)ap0;
    float4 ra1 = *(const float4*)ap1;
    float4 rb0 = *(const float4*)bq0;
    float4 rb1 = *(const float4*)bq1;

    for (int tl = 0; tl < 16; tl++) {
        sm.g.As[ak0 + 0][ar0] = ra0.x; sm.g.As[ak0 + 1][ar0] = ra0.y;
        sm.g.As[ak0 + 2][ar0] = ra0.z; sm.g.As[ak0 + 3][ar0] = ra0.w;
        sm.g.As[ak1 + 0][ar1] = ra1.x; sm.g.As[ak1 + 1][ar1] = ra1.y;
        sm.g.As[ak1 + 2][ar1] = ra1.z; sm.g.As[ak1 + 3][ar1] = ra1.w;
        *(float4*)&sm.g.Bs[br0][bc0] = rb0;
        *(float4*)&sm.g.Bs[br1][bc1] = rb1;
        __syncthreads();

        if (tl < 15) {
            const int ko = (tl + 1) * 16;
            ra0 = *(const float4*)(ap0 + ko);
            ra1 = *(const float4*)(ap1 + ko);
            rb0 = *(const float4*)(bq0 + (size_t)ko * NG);
            rb1 = *(const float4*)(bq1 + (size_t)ko * NG);
        }

#pragma unroll
        for (int k = 0; k < 16; k++) {
            float a[8];
            *(float4*)&a[0] = *(float4*)&sm.g.As[k][ty * 4];
            *(float4*)&a[4] = *(float4*)&sm.g.As[k][64 + ty * 4];
            ull bp[4];
            bp[0] = *(const ull*)&sm.g.Bs[k][tx * 4];
            bp[1] = *(const ull*)&sm.g.Bs[k][tx * 4 + 2];
            bp[2] = *(const ull*)&sm.g.Bs[k][64 + tx * 4];
            bp[3] = *(const ull*)&sm.g.Bs[k][64 + tx * 4 + 2];
            ull ad[8];
#pragma unroll
            for (int i = 0; i < 8; i++) ad[i] = pack2(a[i], a[i]);
#pragma unroll
            for (int i = 0; i < 8; i++)
#pragma unroll
                for (int p = 0; p < 4; p++)
                    ffma2(acc[i][p], ad[i], bp[p]);
        }
        __syncthreads();
    }

#pragma unroll
    for (int ih = 0; ih < 2; ih++)
#pragma unroll
    for (int ii = 0; ii < 4; ii++) {
        int m = m0 + ih * 64 + ty * 4 + ii;
        int i = ih * 4 + ii;
#pragma unroll
        for (int jh = 0; jh < 2; jh++) {
            int n = n0 + jh * 64 + tx * 4;
            float4 v;
            unpack2(acc[i][jh * 2 + 0], v.x, v.y);
            unpack2(acc[i][jh * 2 + 1], v.z, v.w);
            *(float4*)&P[(size_t)m * NG + n] = v;
        }
    }
}

// ---------------------------------------------------------------------------
// Logits role (256 thr): 32 rows/block in 4 groups of 8; 2-way k-split.
// 16 blocks. lt = emitted timestep; reads g_h[(lt+1)&1].
// ---------------------------------------------------------------------------
__device__ void do_logits256(GemmSM& sm,
                             const float* __restrict__ sw,
                             const float* __restrict__ sb,
                             float* __restrict__ out, int lt, int lbid)
{
    const int tid = threadIdx.x;          // 256
    const int j   = tid & 127;
    const int kq  = tid >> 7;             // 0/1
    const float* __restrict__ h = g_h[(lt + 1) & 1];
    const float bj = sb[j];

    for (int grp = 0; grp < 4; grp++) {
        const int b0 = lbid * 32 + grp * 8;

#pragma unroll
        for (int r = 0; r < 8; r++) {
#pragma unroll
            for (int kk = 0; kk < 2; kk++) {
                int k = tid + kk * 256;
                float v = h[(size_t)(b0 + r) * NR + k];
                ((float*)&sm.l.hsp[r >> 1][k])[r & 1] = v;
            }
        }
        __syncthreads();

        ull acc[4] = {0ull, 0ull, 0ull, 0ull};
        const int kbase = kq << 8;
#pragma unroll 8
        for (int kk = 0; kk < 256; kk++) {
            int k = kbase + kk;
            float w = sw[(size_t)k * NC + j];
            ull wd = pack2(w, w);
#pragma unroll
            for (int p = 0; p < 4; p++)
                ffma2(acc[p], wd, *(const ull*)&sm.l.hsp[p][k]);
        }
        if (kq) {
#pragma unroll
            for (int p = 0; p < 4; p++) {
                float x, y; unpack2(acc[p], x, y);
                sm.l.part[p][j] = make_float2(x, y);
            }
        }
        __syncthreads();
        if (!kq) {
#pragma unroll
            for (int p = 0; p < 4; p++) {
                float x, y; unpack2(acc[p], x, y);
                float2 p1 = sm.l.part[p][j];
                sm.l.lgs[2 * p + 0][j] = x + p1.x + bj;
                sm.l.lgs[2 * p + 1][j] = y + p1.y + bj;
            }
        }
        __syncthreads();

        {   // argmax: 8 warps -> 8 rows, first-max tie rule
            const int wid = tid >> 5, lane = tid & 31;
            float best = -INFINITY; int bi = 0;
            const int cbase = lane * 4;
#pragma unroll
            for (int cc = 0; cc < 4; cc++) {
                float v = sm.l.lgs[wid][cbase + cc];
                if (v > best) { best = v; bi = cbase + cc; }
            }
#pragma unroll
            for (int off = 16; off; off >>= 1) {
                float ov = __shfl_down_sync(0xffffffffu, best, off);
                int   oi = __shfl_down_sync(0xffffffffu, bi,   off);
                if (ov > best || (ov == best && oi < bi)) { best = ov; bi = oi; }
            }
            if (lane == 0) sm.l.amax[wid] = bi;
        }
        __syncthreads();

#pragma unroll
        for (int rr = 0; rr < 4; rr++) {
            int r = kq * 4 + rr;
            out[((size_t)(b0 + r) * NT + lt) * NC + j] = (j == sm.l.amax[r]) ? 1.f : 0.f;
        }
        __syncthreads();   // protect smem before next group
    }
}

// ---------------------------------------------------------------------------
// k_gemm: 144 blocks x 256 thr. bid<128 -> partial GEMM; bid>=128 -> logits(t-1)
// (GEMM reads g_h[t&1]; logits(t-1) reads the same buffer -> no hazard.)
// ---------------------------------------------------------------------------
__global__ void __launch_bounds__(256) k_gemm(
    const float* __restrict__ rec,
    const float* __restrict__ sw,
    const float* __restrict__ sb,
    float* __restrict__ out, int t)
{
    __shared__ GemmSM sm;
    const int bid = blockIdx.x;
    if (bid < 128) {
        do_gemm(sm, rec, t, bid);
    } else if (t > 0) {
        do_logits256(sm, sw, sb, out, t - 1, bid - 128);
    }
}

// ---------------------------------------------------------------------------
// k_gates: z = Z[t] + (P0+P1); LSTM nonlinearity; h_out, c update.
// 128 blocks x 512 thr; thread -> (b, j-quad) with float4 loads.
// ---------------------------------------------------------------------------
__global__ void __launch_bounds__(512) k_gates(int t)
{
    const int gid = blockIdx.x * 512 + threadIdx.x;   // 0..65535
    const int b = gid >> 7;                           // 0..511
    const int j = (gid & 127) * 4;                    // 0..508
    float* __restrict__ h_out = g_h[(t & 1) ^ 1];
    const size_t zb = ((size_t)t * NB + b) * NG + j;
    const size_t pb = (size_t)b * NG + j;

    float4 z[4];
#pragma unroll
    for (int g = 0; g < 4; g++) {
        float4 zz = *(const float4*)&g_Z[zb + g * NR];
        float4 p0 = *(const float4*)&g_P[0][pb + g * NR];
        float4 p1 = *(const float4*)&g_P[1][pb + g * NR];
        z[g].x = zz.x + (p0.x + p1.x);
        z[g].y = zz.y + (p0.y + p1.y);
        z[g].z = zz.z + (p0.z + p1.z);
        z[g].w = zz.w + (p0.w + p1.w);
    }
    const int ci = b * NR + j;
    float4 cold = *(const float4*)&g_c[ci];
    float4 cn, hn;
    {
        float si = 1.f / (1.f + expf(-z[0].x));
        float sf = 1.f / (1.f + expf(-z[1].x));
        float so = 1.f / (1.f + expf(-z[3].x));
        float tg = tanhf(z[2].x);
        cn.x = sf * cold.x + si * tg;
        hn.x = so * tanhf(cn.x);
    }
    {
        float si = 1.f / (1.f + expf(-z[0].y));
        float sf = 1.f / (1.f + expf(-z[1].y));
        float so = 1.f / (1.f + expf(-z[3].y));
        float tg = tanhf(z[2].y);
        cn.y = sf * cold.y + si * tg;
        hn.y = so * tanhf(cn.y);
    }
    {
        float si = 1.f / (1.f + expf(-z[0].z));
        float sf = 1.f / (1.f + expf(-z[1].z));
        float so = 1.f / (1.f + expf(-z[3].z));
        float tg = tanhf(z[2].z);
        cn.z = sf * cold.z + si * tg;
        hn.z = so * tanhf(cn.z);
    }
    {
        float si = 1.f / (1.f + expf(-z[0].w));
        float sf = 1.f / (1.f + expf(-z[1].w));
        float so = 1.f / (1.f + expf(-z[3].w));
        float tg = tanhf(z[2].w);
        cn.w = sf * cold.w + si * tg;
        hn.w = so * tanhf(cn.w);
    }
    *(float4*)&g_c[ci] = cn;
    *(float4*)&h_out[ci] = hn;
}

// ---------------------------------------------------------------------------
// Tail: blocks 0..15 logits(NT-1); blocks 16..31 finalize h/c copy (float4).
// ---------------------------------------------------------------------------
__global__ void __launch_bounds__(256) k_tail(
    const float* __restrict__ sw,
    const float* __restrict__ sb,
    float* __restrict__ out)
{
    __shared__ GemmSM sm;
    const int bid = blockIdx.x;
    if (bid < 16) {
        do_logits256(sm, sw, sb, out, NT - 1, bid);
    } else {
        float* oh = out + (size_t)NB * NT * NC;
        float* oc = oh + (size_t)NB * NR;
        const int n4 = NB * NR / 4;                 // 65536 float4s
        for (int i = (bid - 16) * 256 + threadIdx.x; i < n4; i += 16 * 256) {
            ((float4*)oh)[i] = ((const float4*)g_h[0])[i];   // NT & 1 == 0
            ((float4*)oc)[i] = ((const float4*)g_c)[i];
        }
    }
}

// ---------------------------------------------------------------------------
extern "C" void kernel_launch(void* const* d_in, const int* in_sizes, int n_in,
                              void* d_out, int out_size)
{
    const float* f_pool = (const float*)d_in[0];
    const float* gt     = (const float*)d_in[1];
    const float* W      = (const float*)d_in[2];
    const float* rec    = (const float*)d_in[3];
    const float* bias   = (const float*)d_in[4];
    const float* sw     = (const float*)d_in[5];
    const float* sb     = (const float*)d_in[6];
    float* out = (float*)d_out;

    k_init<<<(NB * NR + 255) / 256, 256>>>();
    k_precompute<<<dim3(16, 128), 256>>>(f_pool, gt, W, bias);
    for (int t = 0; t < NT; t++) {
        k_gemm<<<144, 256>>>(rec, sw, sb, out, t);
        k_gates<<<128, 512>>>(t);
    }
    k_tail<<<32, 256>>>(sw, sb, out);
}